// round 15
// baseline (speedup 1.0000x reference)
#include <cuda_runtime.h>
#include <math.h>
#include <stdint.h>

#define BQ 8
#define LQ 1024
#define HQ 512
#define ML (BQ * LQ)   // 8192 rows

static const int NUM_LAYERS = 3;

// ---------------- static scratch (no allocations allowed) ----------------
__device__ float g_h[ML * HQ];
__device__ float g_c[ML * HQ];
__device__ float g_c2[ML * HQ];          // c double buffer
__device__ float g_emb[ML * HQ];
__device__ float g_wecat[ML * 8 * HQ];   // 134 MB
__device__ float g_gates[ML * 8 * HQ];   // 134 MB
__device__ float g_gf[ML * HQ];
__device__ float g_stat[ML * 2];         // per-row LN stats for gf
__device__ float g_r[ML * 2 * HQ];
__device__ float g_outpre[ML * HQ];
__device__ float g_dh[BQ * HQ];
__device__ float g_dc[BQ * HQ];
__device__ float g_avg[BQ * HQ];
__device__ float g_gd[BQ * HQ];
__device__ float g_gdo[BQ * HQ];
__device__ float g_dxf[BQ * HQ];
__device__ float g_dext[BQ * 8 * HQ];    // per-batch d_in@Wg3 + bg
__device__ float g_lens[BQ];

__device__ __forceinline__ float sigmoidf_(float x) { return 1.f / (1.f + expf(-x)); }

__device__ __forceinline__ void warpRed2(float& s, float& q) {
#pragma unroll
    for (int o = 16; o > 0; o >>= 1) {
        s += __shfl_down_sync(0xffffffffu, s, o);
        q += __shfl_down_sync(0xffffffffu, q, o);
    }
}

__device__ __forceinline__ uint32_t f2tf(float f) {
    uint32_t u;
    asm("cvt.rna.tf32.f32 %0, %1;" : "=r"(u) : "f"(f));
    return u;
}

__device__ __forceinline__ void mma_tf32(float* c, const uint32_t* a, const uint32_t* b) {
    asm volatile(
        "mma.sync.aligned.m16n8k8.row.col.f32.tf32.tf32.f32 "
        "{%0,%1,%2,%3}, {%4,%5,%6,%7}, {%8,%9}, {%0,%1,%2,%3};\n"
        : "+f"(c[0]), "+f"(c[1]), "+f"(c[2]), "+f"(c[3])
        : "r"(a[0]), "r"(a[1]), "r"(a[2]), "r"(a[3]), "r"(b[0]), "r"(b[1]));
}

// Synthesize the concat row [h, hb, ha] element block (float4) on the fly.
// col in [0, 1536): block 0 = h, block 1 = (h[-1]+h[-2])*sm, block 2 = (h[+1]+h[+2])*sm.
__device__ __forceinline__ float4 loadConcat(const float* __restrict__ h, size_t rowBase,
                                             int l, float sm, int col)
{
    const int c0 = col >> 9;
    const int j = col & 511;
    const float* p = h + rowBase + j;
    if (c0 == 0) return *(const float4*)p;
    float4 r = make_float4(0.f, 0.f, 0.f, 0.f);
    if (c0 == 1) {
        if (l >= 1) {
            float4 t = *(const float4*)(p - HQ);
            r.x = t.x; r.y = t.y; r.z = t.z; r.w = t.w;
        }
        if (l >= 2) {
            float4 t = *(const float4*)(p - 2 * HQ);
            r.x += t.x; r.y += t.y; r.z += t.z; r.w += t.w;
        }
    } else {
        if (l + 1 < LQ) {
            float4 t = *(const float4*)(p + HQ);
            r.x = t.x; r.y = t.y; r.z = t.z; r.w = t.w;
        }
        if (l + 2 < LQ) {
            float4 t = *(const float4*)(p + 2 * HQ);
            r.x += t.x; r.y += t.y; r.z += t.z; r.w += t.w;
        }
    }
    r.x *= sm; r.y *= sm; r.z *= sm; r.w *= sm;
    return r;
}

// ---------------- TF32 tensor-core GEMM: C[M,N] = A[M,K] @ B[K,N] ----------------
// 128x128 block tile, 256 threads (8 warps, 2x4), 64x32 per warp (4x4 m16n8k8),
// BK=16, single smem buffer + register prefetch, conflict-free k-major smem.
// CONCAT != 0: A is virtual [h, hb, ha] built from Hsrc + mask (K must be 1536).
// epilogue: + bias[n] + extra[(m/extraDiv)*N+n] + extra2[(m/extra2Div)*N+n] (all opt),
// act: 0 none, 1 tanh, 2 relu
template <int CONCAT>
__global__ void __launch_bounds__(256, 2)
gemm_tf32_kernel_t(const float* __restrict__ A, const float* __restrict__ Bm,
                   float* __restrict__ C, int M, int N, int K,
                   const float* __restrict__ bias, const float* __restrict__ extra,
                   int extraDiv, int act,
                   const float* __restrict__ extra2, int extra2Div,
                   const float* __restrict__ maskp)
{
    __shared__ float As[16][132];   // [k][m], padded
    __shared__ float Bs[16][132];   // [k][n], padded

    const int tid = threadIdx.x;
    const int bm = blockIdx.y * 128;
    const int bn = blockIdx.x * 128;
    const int lane = tid & 31;
    const int warp = tid >> 5;
    const int wm = (warp & 1) * 64;
    const int wn = (warp >> 1) * 32;
    const int g = lane >> 2;          // groupID (0..7)
    const int q = lane & 3;           // threadID_in_group (0..3)

    // global load mapping
    const int arow = tid >> 2;        // 0..63
    const int acol = (tid & 3) * 4;   // 0,4,8,12
    const int bkrow = tid >> 5;       // 0..7
    const int bcol = (tid & 31) * 4;

    const int m0 = bm + arow;
    const int m1 = m0 + 64;
    const int l0 = m0 & (LQ - 1);
    const int l1 = m1 & (LQ - 1);
    float sm0 = 0.f, sm1 = 0.f;
    size_t rb0 = 0, rb1 = 0;
    const float* Ap = nullptr;
    const float* Ap2 = nullptr;
    if (CONCAT) {
        sm0 = 1.f - maskp[m0];
        sm1 = 1.f - maskp[m1];
        rb0 = (size_t)m0 * HQ;
        rb1 = (size_t)m1 * HQ;
    } else {
        Ap = A + (size_t)m0 * K + acol;
        Ap2 = Ap + (size_t)64 * K;
    }
    const float* Bp  = Bm + (size_t)bkrow * N + bn + bcol;
    const float* Bp2 = Bp + (size_t)8 * N;

    float4 a0v, a1v;
    if (CONCAT) {
        a0v = loadConcat(A, rb0, l0, sm0, acol);
        a1v = loadConcat(A, rb1, l1, sm1, acol);
    } else {
        a0v = *(const float4*)Ap;
        a1v = *(const float4*)Ap2;
    }
    float4 b0v = *(const float4*)Bp;
    float4 b1v = *(const float4*)Bp2;

    float acc[4][4][4];
#pragma unroll
    for (int i = 0; i < 4; i++)
#pragma unroll
        for (int j = 0; j < 4; j++)
#pragma unroll
            for (int k = 0; k < 4; k++) acc[i][j][k] = 0.f;

    int k0 = 0;
    for (;;) {
        As[acol + 0][arow] = a0v.x;
        As[acol + 1][arow] = a0v.y;
        As[acol + 2][arow] = a0v.z;
        As[acol + 3][arow] = a0v.w;
        As[acol + 0][arow + 64] = a1v.x;
        As[acol + 1][arow + 64] = a1v.y;
        As[acol + 2][arow + 64] = a1v.z;
        As[acol + 3][arow + 64] = a1v.w;
        *(float4*)&Bs[bkrow][bcol] = b0v;
        *(float4*)&Bs[bkrow + 8][bcol] = b1v;
        __syncthreads();

        k0 += 16;
        if (k0 < K) {
            if (CONCAT) {
                a0v = loadConcat(A, rb0, l0, sm0, acol + k0);
                a1v = loadConcat(A, rb1, l1, sm1, acol + k0);
            } else {
                a0v = *(const float4*)(Ap + k0);
                a1v = *(const float4*)(Ap2 + k0);
            }
            b0v = *(const float4*)(Bp + (size_t)k0 * N);
            b1v = *(const float4*)(Bp2 + (size_t)k0 * N);
        }

#pragma unroll
        for (int kk = 0; kk < 16; kk += 8) {
            const int kq = kk + q;
            uint32_t af[4][4];
            uint32_t bf[4][2];
#pragma unroll
            for (int mt = 0; mt < 4; mt++) {
                const int mr = wm + mt * 16 + g;
                af[mt][0] = f2tf(As[kq][mr]);
                af[mt][1] = f2tf(As[kq][mr + 8]);
                af[mt][2] = f2tf(As[kq + 4][mr]);
                af[mt][3] = f2tf(As[kq + 4][mr + 8]);
            }
#pragma unroll
            for (int nt = 0; nt < 4; nt++) {
                const int nc = wn + nt * 8 + g;
                bf[nt][0] = f2tf(Bs[kq][nc]);
                bf[nt][1] = f2tf(Bs[kq + 4][nc]);
            }
#pragma unroll
            for (int mt = 0; mt < 4; mt++)
#pragma unroll
                for (int nt = 0; nt < 4; nt++)
                    mma_tf32(acc[mt][nt], af[mt], bf[nt]);
        }
        if (k0 >= K) break;
        __syncthreads();
    }

    // epilogue
#pragma unroll
    for (int mt = 0; mt < 4; mt++) {
        const int r0 = bm + wm + mt * 16 + g;
#pragma unroll
        for (int half = 0; half < 2; half++) {
            const int m = r0 + half * 8;
            const size_t rowOff = (size_t)m * N;
            const size_t erow = extra ? (size_t)(m / extraDiv) * N : 0;
            const size_t e2row = extra2 ? (size_t)(m / extra2Div) * N : 0;
#pragma unroll
            for (int nt = 0; nt < 4; nt++) {
                const int n = bn + wn + nt * 8 + q * 2;
                float v0 = acc[mt][nt][half * 2 + 0];
                float v1 = acc[mt][nt][half * 2 + 1];
                if (bias) { v0 += bias[n]; v1 += bias[n + 1]; }
                if (extra) { v0 += extra[erow + n]; v1 += extra[erow + n + 1]; }
                if (extra2) { v0 += extra2[e2row + n]; v1 += extra2[e2row + n + 1]; }
                if (act == 1) { v0 = tanhf(v0); v1 = tanhf(v1); }
                else if (act == 2) { v0 = fmaxf(v0, 0.f); v1 = fmaxf(v1, 0.f); }
                float2 o; o.x = v0; o.y = v1;
                *(float2*)&C[rowOff + n] = o;
            }
        }
    }
}

// ---------------- pointwise kernels ----------------

__global__ void init_kernel(const float* __restrict__ w, const float* __restrict__ mask,
                            float* __restrict__ h, float* __restrict__ c)
{
    int idx = blockIdx.x * blockDim.x + threadIdx.x;
    int row = idx / HQ;
    float sm = 1.f - mask[row];
    float v = w[idx] * sm;
    h[idx] = v;
    c[idx] = v;
}

__global__ void lens_kernel(const float* __restrict__ mask, float* __restrict__ lens)
{
    int b = blockIdx.x, t = threadIdx.x;
    float s = 0.f;
    for (int l = t; l < LQ; l += 256) s += 1.f - mask[b * LQ + l];
    float dummy = 0.f;
    warpRed2(s, dummy);
    __shared__ float ws[8];
    if ((t & 31) == 0) ws[t >> 5] = s;
    __syncthreads();
    if (t == 0) {
        float S = 0.f;
        for (int w = 0; w < 8; w++) S += ws[w];
        lens[b] = S;
    }
}

// out[b,h] = sum_l in[b,l,h] / lens[b]  (o2 optional duplicate)
__global__ void colmean_kernel(const float* __restrict__ in, float* __restrict__ o1,
                               float* __restrict__ o2, const float* __restrict__ lens)
{
    int b = blockIdx.y;
    int hh = blockIdx.x * blockDim.x + threadIdx.x;
    const float* p = in + (size_t)b * LQ * HQ + hh;
    float s = 0.f;
#pragma unroll 8
    for (int l = 0; l < LQ; l++) s += p[(size_t)l * HQ];
    s /= lens[b];
    o1[b * HQ + hh] = s;
    if (o2) o2[b * HQ + hh] = s;
}

// dext[b][n] = bg[n] + sum_i dh[b][i] * Wg[3H+i][n]   (rank-8 d_in contribution, exact fp32)
__global__ void dext_kernel(const float* __restrict__ dh, const float* __restrict__ Wg,
                            const float* __restrict__ bg, float* __restrict__ dext)
{
    int b = blockIdx.y;
    int n = blockIdx.x * 256 + threadIdx.x;    // grid.x = 16 -> 4096 cols
    __shared__ float ds[HQ];
    for (int i = threadIdx.x; i < HQ; i += 256) ds[i] = dh[b * HQ + i];
    __syncthreads();
    const float* W = Wg + (size_t)3 * HQ * (8 * HQ) + n;
    float s = bg[n];
#pragma unroll 8
    for (int i = 0; i < HQ; i++) s += ds[i] * W[(size_t)i * (8 * HQ)];
    dext[(size_t)b * 8 * HQ + n] = s;
}

// Per-(b,l)-row gate math: 7 LayerNorms over H, sigmoids, 5-way softmax, cell/hidden update.
// cb/ca window sums computed inline from cOld; writes cNew (double buffer, no race).
__global__ void gate_kernel(const float* __restrict__ gates,
                            const float* __restrict__ cOld, float* __restrict__ cNew,
                            float* __restrict__ h,
                            const float* __restrict__ emb, const float* __restrict__ dc,
                            const float* __restrict__ mask,
                            const float* __restrict__ lng, const float* __restrict__ lnb)
{
    int row = blockIdx.x;
    int b = row / LQ;
    int l = row & (LQ - 1);
    int t = threadIdx.x;
    float sm = 1.f - mask[row];
    const float* g = gates + (size_t)row * (8 * HQ);
    float v[8][2];
#pragma unroll
    for (int cc = 0; cc < 8; cc++) {
        v[cc][0] = g[cc * HQ + t];
        v[cc][1] = g[cc * HQ + t + 256];
    }
    __shared__ float ws[7][8], wq[7][8];
    __shared__ float smu[8], srs[8];
    const int cids[7] = {0, 1, 2, 3, 4, 5, 7};
    int lane = t & 31, warp = t >> 5;
#pragma unroll
    for (int ci = 0; ci < 7; ci++) {
        int cc = cids[ci];
        float s = v[cc][0] + v[cc][1];
        float q = v[cc][0] * v[cc][0] + v[cc][1] * v[cc][1];
        warpRed2(s, q);
        if (lane == 0) { ws[ci][warp] = s; wq[ci][warp] = q; }
    }
    __syncthreads();
    if (t < 7) {
        float S = 0.f, Q = 0.f;
#pragma unroll
        for (int w = 0; w < 8; w++) { S += ws[t][w]; Q += wq[t][w]; }
        float mu = S * (1.f / HQ);
        float var = Q * (1.f / HQ) - mu * mu;
        smu[cids[t]] = mu;
        srs[cids[t]] = rsqrtf(var + 1e-5f);
    }
    __syncthreads();
#pragma unroll
    for (int e = 0; e < 2; e++) {
        int j = t + e * 256;
        size_t idx = (size_t)row * HQ + j;
#define LNF(val, cc, li) (lng[(li) * HQ + j] * ((val) - smu[cc]) * srs[cc] + lnb[(li) * HQ + j])
        float gfl = sigmoidf_(LNF(v[0][e], 0, 3));
        float gfr = sigmoidf_(LNF(v[1][e], 1, 4));
        float gfc = sigmoidf_(LNF(v[2][e], 2, 5));
        float gfd = sigmoidf_(LNF(v[3][e], 3, 6));
        float gi  = sigmoidf_(LNF(v[4][e], 4, 0));
        float ge  = sigmoidf_(LNF(v[5][e], 5, 2));
        float go  = sigmoidf_(LNF(v[7][e], 7, 1));
#undef LNF
        float cand = tanhf(v[6][e]);
        float m5 = fmaxf(fmaxf(fmaxf(gfl, gfr), fmaxf(gfc, gfd)), gi);
        float e0 = expf(gfl - m5), e1 = expf(gfr - m5), e2 = expf(gfc - m5);
        float e3 = expf(gfd - m5), e4 = expf(gi - m5);
        float inv = 1.f / (e0 + e1 + e2 + e3 + e4);
        // inline window sums of cOld (KERNEL_SIZE=2), same math as old build_kernel
        float c1 = (l >= 1) ? cOld[idx - (size_t)HQ] : 0.f;
        float c2 = (l >= 2) ? cOld[idx - (size_t)2 * HQ] : 0.f;
        float c3 = (l + 1 < LQ) ? cOld[idx + (size_t)HQ] : 0.f;
        float c4 = (l + 2 < LQ) ? cOld[idx + (size_t)2 * HQ] : 0.f;
        float cb = (c1 + c2) * sm;
        float ca = (c3 + c4) * sm;
        float cold = cOld[idx];
        float cn = (e0 * cb + e1 * ca + e2 * cold + e3 * dc[b * HQ + j] + e4 * cand) * inv;
        float hn = go * tanhf(cn) + ge * emb[idx];
        h[idx] = hn * sm;
        cNew[idx] = cn * sm;
    }
}

// Tiny decoder matmuls (B=8 rows): g_d, g_do (LN+sigmoid over H), dxf = dh@gWxf
__global__ void small_mm_kernel(const float* __restrict__ dh, const float* __restrict__ avg,
                                const float* __restrict__ Wdg, const float* __restrict__ bdg,
                                const float* __restrict__ Wdf,
                                const float* __restrict__ lng, const float* __restrict__ lnb,
                                float* __restrict__ gd, float* __restrict__ gdo,
                                float* __restrict__ dxf)
{
    int b = blockIdx.x, j = threadIdx.x;   // 512 threads
    __shared__ float ds[HQ], as_[HQ];
    ds[j] = dh[b * HQ + j];
    as_[j] = avg[b * HQ + j];
    __syncthreads();
    float ad = bdg[j], ao = bdg[HQ + j], af = 0.f;
#pragma unroll 4
    for (int i = 0; i < HQ; i++) {
        float d = ds[i], a = as_[i];
        const float* w0 = Wdg + (size_t)i * 2 * HQ;
        const float* w1 = Wdg + (size_t)(HQ + i) * 2 * HQ;
        ad += d * w0[j] + a * w1[j];
        ao += d * w0[HQ + j] + a * w1[HQ + j];
        af += d * Wdf[(size_t)i * HQ + j];
    }
    __shared__ float ws[16], wq[16];
    __shared__ float stat[4];
    int lane = j & 31, warp = j >> 5;
    float s = ad, q = ad * ad;
    warpRed2(s, q);
    if (lane == 0) { ws[warp] = s; wq[warp] = q; }
    __syncthreads();
    if (j == 0) {
        float S = 0.f, Q = 0.f;
        for (int w = 0; w < 16; w++) { S += ws[w]; Q += wq[w]; }
        float mu = S * (1.f / HQ);
        stat[0] = mu;
        stat[1] = rsqrtf(Q * (1.f / HQ) - mu * mu + 1e-5f);
    }
    __syncthreads();
    float gdv = sigmoidf_(lng[7 * HQ + j] * (ad - stat[0]) * stat[1] + lnb[7 * HQ + j]);
    __syncthreads();
    s = ao; q = ao * ao;
    warpRed2(s, q);
    if (lane == 0) { ws[warp] = s; wq[warp] = q; }
    __syncthreads();
    if (j == 0) {
        float S = 0.f, Q = 0.f;
        for (int w = 0; w < 16; w++) { S += ws[w]; Q += wq[w]; }
        float mu = S * (1.f / HQ);
        stat[2] = mu;
        stat[3] = rsqrtf(Q * (1.f / HQ) - mu * mu + 1e-5f);
    }
    __syncthreads();
    float gdov = sigmoidf_(lng[8 * HQ + j] * (ao - stat[2]) * stat[3] + lnb[8 * HQ + j]);
    gd[b * HQ + j] = gdv;
    gdo[b * HQ + j] = gdov;
    dxf[b * HQ + j] = af;
}

// Row LayerNorm over H, optional sigmoid, optional seq_mask multiply.
__global__ void rowln_kernel(const float* __restrict__ in, float* __restrict__ out,
                             const float* __restrict__ lng, const float* __restrict__ lnb,
                             int lnidx, int act, const float* __restrict__ mask)
{
    int row = blockIdx.x, t = threadIdx.x;  // 256 threads
    const float* r = in + (size_t)row * HQ;
    float v0 = r[t], v1 = r[t + 256];
    float s = v0 + v1, q = v0 * v0 + v1 * v1;
    warpRed2(s, q);
    __shared__ float ws[8], wq[8], stat[2];
    int lane = t & 31, warp = t >> 5;
    if (lane == 0) { ws[warp] = s; wq[warp] = q; }
    __syncthreads();
    if (t == 0) {
        float S = 0.f, Q = 0.f;
        for (int w = 0; w < 8; w++) { S += ws[w]; Q += wq[w]; }
        float mu = S * (1.f / HQ);
        stat[0] = mu;
        stat[1] = rsqrtf(Q * (1.f / HQ) - mu * mu + 1e-5f);
    }
    __syncthreads();
    float mu = stat[0], rs = stat[1];
    float msc = mask ? (1.f - mask[row]) : 1.f;
    float y0 = lng[lnidx * HQ + t] * (v0 - mu) * rs + lnb[lnidx * HQ + t];
    float y1 = lng[lnidx * HQ + t + 256] * (v1 - mu) * rs + lnb[lnidx * HQ + t + 256];
    if (act == 1) { y0 = sigmoidf_(y0); y1 = sigmoidf_(y1); }
    out[(size_t)row * HQ + t] = y0 * msc;
    out[(size_t)row * HQ + t + 256] = y1 * msc;
}

// Per-row LN stats only (mu, rsqrt(var+eps)) -> stat[row*2 + {0,1}]
__global__ void rowstat_kernel(const float* __restrict__ in, float* __restrict__ stat)
{
    int row = blockIdx.x, t = threadIdx.x;  // 256 threads
    const float* r = in + (size_t)row * HQ;
    float v0 = r[t], v1 = r[t + 256];
    float s = v0 + v1, q = v0 * v0 + v1 * v1;
    warpRed2(s, q);
    __shared__ float ws[8], wq[8];
    int lane = t & 31, warp = t >> 5;
    if (lane == 0) { ws[warp] = s; wq[warp] = q; }
    __syncthreads();
    if (t == 0) {
        float S = 0.f, Q = 0.f;
        for (int w = 0; w < 8; w++) { S += ws[w]; Q += wq[w]; }
        float mu = S * (1.f / HQ);
        stat[row * 2 + 0] = mu;
        stat[row * 2 + 1] = rsqrtf(Q * (1.f / HQ) - mu * mu + 1e-5f);
    }
}

// Softmax over the L+1 axis per (b,h) column; LN+sigmoid of raw gf applied on the fly
// via per-row stats. All candidates <= 1 (sigmoid outputs), fixed max of 1.0.
__global__ void colsoft_kernel(const float* __restrict__ gfraw, const float* __restrict__ stat,
                               const float* __restrict__ cbuf,
                               const float* __restrict__ gd, const float* __restrict__ gdo,
                               const float* __restrict__ mask,
                               float* __restrict__ dc, float* __restrict__ dh,
                               const float* __restrict__ lng, const float* __restrict__ lnb)
{
    int b = blockIdx.y;
    int hh = blockIdx.x * blockDim.x + threadIdx.x;
    const float* gp = gfraw + (size_t)b * LQ * HQ + hh;
    const float* cp = cbuf + (size_t)b * LQ * HQ + hh;
    const float* mp = mask + b * LQ;
    const float* sp = stat + (size_t)b * LQ * 2;
    const float lg = lng[9 * HQ + hh];
    const float lb = lnb[9 * HQ + hh];
    float s = 0.f, acc = 0.f;
#pragma unroll 4
    for (int l = 0; l < LQ; l++) {
        float mu = sp[l * 2 + 0], rs = sp[l * 2 + 1];
        float gfv = sigmoidf_(lg * (gp[(size_t)l * HQ] - mu) * rs + lb);
        float v = gfv - mp[l] * 1e25f;
        float e = expf(v - 1.f);
        s += e;
        acc += e * cp[(size_t)l * HQ];
    }
    float dcold = dc[b * HQ + hh];
    float eg = expf(gd[b * HQ + hh] - 1.f);
    s += eg;
    acc += eg * dcold;
    float dcn = acc / s;
    dc[b * HQ + hh] = dcn;
    dh[b * HQ + hh] = gdo[b * HQ + hh] * tanhf(dcn);
}

// ---------------- host side ----------------

static void gemm(const float* A, const float* Bm, float* C, int M, int N, int K,
                 const float* bias, const float* extra, int extraDiv, int act,
                 const float* extra2 = nullptr, int extra2Div = 1)
{
    dim3 grid(N / 128, M / 128);
    gemm_tf32_kernel_t<0><<<grid, 256>>>(A, Bm, C, M, N, K, bias, extra, extraDiv, act,
                                         extra2, extra2Div, nullptr);
}

static void gemm_concat(const float* h, const float* mask, const float* Bm, float* C,
                        int M, int N, const float* extra, const float* extra2, int extra2Div)
{
    dim3 grid(N / 128, M / 128);
    gemm_tf32_kernel_t<1><<<grid, 256>>>(h, Bm, C, M, N, 3 * HQ, nullptr, extra, 1, 0,
                                         extra2, extra2Div, mask);
}

#define SYM(var, symbol) do { void* _p = nullptr; cudaGetSymbolAddress(&_p, symbol); var = (float*)_p; } while (0)

extern "C" void kernel_launch(void* const* d_in, const int* in_sizes, int n_in,
                              void* d_out, int out_size)
{
    (void)in_sizes; (void)n_in; (void)out_size;
    const float* word = (const float*)d_in[0];
    const float* mask = (const float*)d_in[1];
    // d_in[2] = num_layers (int32, value 3) -> loop count must be host-constant for graph capture
    const float* Wg   = (const float*)d_in[3];
    const float* bg   = (const float*)d_in[4];
    const float* Wemb = (const float*)d_in[5];
    const float* Wdg  = (const float*)d_in[6];
    const float* bdg  = (const float*)d_in[7];
    const float* Wdf  = (const float*)d_in[8];
    const float* bdf  = (const float*)d_in[9];
    const float* Wet  = (const float*)d_in[10];
    const float* bet  = (const float*)d_in[11];
    const float* W1   = (const float*)d_in[12];
    const float* b1   = (const float*)d_in[13];
    const float* W2   = (const float*)d_in[14];
    const float* b2   = (const float*)d_in[15];
    const float* lng  = (const float*)d_in[16];
    const float* lnb  = (const float*)d_in[17];
    float* out = (float*)d_out;

    float *h, *c, *c2, *emb, *wecat, *gates, *gf, *stat, *r, *outpre;
    float *dh, *dc, *avg, *gd, *gdo, *dxf, *dext, *lens;
    SYM(h, g_h); SYM(c, g_c); SYM(c2, g_c2); SYM(emb, g_emb); SYM(wecat, g_wecat);
    SYM(gates, g_gates); SYM(gf, g_gf); SYM(stat, g_stat);
    SYM(r, g_r); SYM(outpre, g_outpre);
    SYM(dh, g_dh); SYM(dc, g_dc); SYM(avg, g_avg); SYM(gd, g_gd);
    SYM(gdo, g_gdo); SYM(dxf, g_dxf); SYM(dext, g_dext); SYM(lens, g_lens);

    // x = word * seq_mask; h = c = x
    init_kernel<<<(ML * HQ) / 256, 256>>>(word, mask, h, c);
    lens_kernel<<<BQ, 256>>>(mask, lens);
    colmean_kernel<<<dim3(HQ / 256, BQ), 256>>>(h, dh, dc, lens);

    // we_cat = x @ Wemb ;  emb_tr = tanh(x @ Wet + bet)
    gemm(h, Wemb, wecat, ML, 8 * HQ, HQ, nullptr, nullptr, 1, 0);
    gemm(h, Wet, emb, ML, HQ, HQ, bet, nullptr, 1, 1);

    float* cCur = c;
    float* cNext = c2;
    for (int layer = 0; layer < NUM_LAYERS; ++layer) {
        // dext[b] = bg + dh[b] @ Wg[3H:4H]   (rank-8 d_in contribution, fp32)
        dext_kernel<<<dim3(16, BQ), 256>>>(dh, Wg, bg, dext);
        // gates = [h,hb,ha] @ Wg[0:3H] + we_cat + dext[b]   (concat built in the loader)
        gemm_concat(h, mask, Wg, gates, ML, 8 * HQ, wecat, dext, LQ);
        gate_kernel<<<ML, 256>>>(gates, cCur, cNext, h, emb, dc, mask, lng, lnb);
        colmean_kernel<<<dim3(HQ / 256, BQ), 256>>>(h, avg, nullptr, lens);
        small_mm_kernel<<<BQ, HQ>>>(dh, avg, Wdg, bdg, Wdf, lng, lnb, gd, gdo, dxf);
        // pre_f = h @ gWhf + bdf + dxf[b]  (gWhf = Wdf rows H..2H)
        gemm(h, Wdf + (size_t)HQ * HQ, gf, ML, HQ, HQ, bdf, dxf, LQ, 0);
        rowstat_kernel<<<ML, 256>>>(gf, stat);
        colsoft_kernel<<<dim3(HQ / 256, BQ), 256>>>(gf, stat, cNext, gd, gdo, mask, dc, dh,
                                                    lng, lnb);
        float* tmp = cCur; cCur = cNext; cNext = tmp;
    }

    // FFN + residual + final LN * seq_mask
    gemm(h, W1, r, ML, 2 * HQ, HQ, b1, nullptr, 1, 2);           // relu(h@W1+b1)
    gemm(r, W2, outpre, ML, HQ, 2 * HQ, b2, h, 1, 0);            // h + r@W2 + b2
    rowln_kernel<<<ML, 256>>>(outpre, out, lng, lnb, 10, 0, mask);
}

// round 16
// speedup vs baseline: 1.1520x; 1.1520x over previous
#include <cuda_runtime.h>
#include <math.h>
#include <stdint.h>

#define BQ 8
#define LQ 1024
#define HQ 512
#define ML (BQ * LQ)   // 8192 rows

static const int NUM_LAYERS = 3;

// ---------------- static scratch (no allocations allowed) ----------------
__device__ float g_h[ML * HQ];
__device__ float g_c[ML * HQ];
__device__ float g_emb[ML * HQ];
__device__ float g_wecat[ML * 8 * HQ];   // 134 MB
__device__ float g_Acat[ML * 3 * HQ];    // 50 MB  (d_in folded out)
__device__ float g_gates[ML * 8 * HQ];   // 134 MB
__device__ float g_cb[ML * HQ];
__device__ float g_ca[ML * HQ];
__device__ float g_gf[ML * HQ];
__device__ float g_r[ML * 2 * HQ];
__device__ float g_outpre[ML * HQ];
__device__ float g_dh[BQ * HQ];
__device__ float g_dc[BQ * HQ];
__device__ float g_avg[BQ * HQ];
__device__ float g_gd[BQ * HQ];
__device__ float g_gdo[BQ * HQ];
__device__ float g_dxf[BQ * HQ];
__device__ float g_dext[BQ * 8 * HQ];    // per-batch d_in@Wg3 + bg
__device__ float g_lens[BQ];

__device__ __forceinline__ float sigmoidf_(float x) { return 1.f / (1.f + expf(-x)); }

__device__ __forceinline__ void warpRed2(float& s, float& q) {
#pragma unroll
    for (int o = 16; o > 0; o >>= 1) {
        s += __shfl_down_sync(0xffffffffu, s, o);
        q += __shfl_down_sync(0xffffffffu, q, o);
    }
}

__device__ __forceinline__ float f2tf_f(float f) {
    uint32_t u;
    asm("cvt.rna.tf32.f32 %0, %1;" : "=r"(u) : "f"(f));
    return __uint_as_float(u);
}

__device__ __forceinline__ void mma_tf32(float* c, const uint32_t* a, const uint32_t* b) {
    asm volatile(
        "mma.sync.aligned.m16n8k8.row.col.f32.tf32.tf32.f32 "
        "{%0,%1,%2,%3}, {%4,%5,%6,%7}, {%8,%9}, {%0,%1,%2,%3};\n"
        : "+f"(c[0]), "+f"(c[1]), "+f"(c[2]), "+f"(c[3])
        : "r"(a[0]), "r"(a[1]), "r"(a[2]), "r"(a[3]), "r"(b[0]), "r"(b[1]));
}

// ---------------- TF32 tensor-core GEMM: C[M,N] = A[M,K] @ B[K,N] ----------------
// 128x128 block tile, 256 threads (8 warps, 2x4), 64x32 per warp (4x4 m16n8k8),
// BK=16, single smem buffer + register prefetch.
// Pad = 136 floats (136 % 32 == 8): fragment-load banks = (8q + g + c) % 32 ->
// fully conflict-free for both A and B loads. A producer mapped row-contiguous
// per warp (ra = tid&63) so A stores are conflict-free too. tf32 rounding is
// applied at smem-store time (bit-identical to rounding at load time).
// epilogue: + bias[n] + extra[(m/extraDiv)*N+n] + extra2[(m/extra2Div)*N+n] (opt),
// act: 0 none, 1 tanh, 2 relu
__global__ void __launch_bounds__(256)
gemm_tf32_kernel(const float* __restrict__ A, const float* __restrict__ Bm,
                 float* __restrict__ C, int M, int N, int K,
                 const float* __restrict__ bias, const float* __restrict__ extra,
                 int extraDiv, int act,
                 const float* __restrict__ extra2, int extra2Div)
{
    __shared__ float As[16][136];   // [k][m], pad 136 (mod 32 == 8)
    __shared__ float Bs[16][136];   // [k][n]

    const int tid = threadIdx.x;
    const int bm = blockIdx.y * 128;
    const int bn = blockIdx.x * 128;
    const int lane = tid & 31;
    const int warp = tid >> 5;
    const int wm = (warp & 1) * 64;
    const int wn = (warp >> 1) * 32;
    const int g = lane >> 2;          // groupID (0..7)
    const int q = lane & 3;           // threadID_in_group (0..3)

    // A producer: row-contiguous per warp -> conflict-free smem stores
    const int ra = tid & 63;          // 0..63 (32 consecutive rows per warp)
    const int acol = (tid >> 6) * 4;  // 0,4,8,12
    // B producer
    const int bkrow = tid >> 5;       // 0..7
    const int bcol = (tid & 31) * 4;

    const float* Ap  = A + (size_t)(bm + ra) * K + acol;
    const float* Ap2 = Ap + (size_t)64 * K;
    const float* Bp  = Bm + (size_t)bkrow * N + bn + bcol;
    const float* Bp2 = Bp + (size_t)8 * N;

    float4 a0v = *(const float4*)Ap;
    float4 a1v = *(const float4*)Ap2;
    float4 b0v = *(const float4*)Bp;
    float4 b1v = *(const float4*)Bp2;

    float acc[4][4][4];
#pragma unroll
    for (int i = 0; i < 4; i++)
#pragma unroll
        for (int j = 0; j < 4; j++)
#pragma unroll
            for (int k = 0; k < 4; k++) acc[i][j][k] = 0.f;

    int k0 = 0;
    for (;;) {
        As[acol + 0][ra] = f2tf_f(a0v.x);
        As[acol + 1][ra] = f2tf_f(a0v.y);
        As[acol + 2][ra] = f2tf_f(a0v.z);
        As[acol + 3][ra] = f2tf_f(a0v.w);
        As[acol + 0][ra + 64] = f2tf_f(a1v.x);
        As[acol + 1][ra + 64] = f2tf_f(a1v.y);
        As[acol + 2][ra + 64] = f2tf_f(a1v.z);
        As[acol + 3][ra + 64] = f2tf_f(a1v.w);
        {
            float4 r0 = make_float4(f2tf_f(b0v.x), f2tf_f(b0v.y), f2tf_f(b0v.z), f2tf_f(b0v.w));
            float4 r1 = make_float4(f2tf_f(b1v.x), f2tf_f(b1v.y), f2tf_f(b1v.z), f2tf_f(b1v.w));
            *(float4*)&Bs[bkrow][bcol] = r0;
            *(float4*)&Bs[bkrow + 8][bcol] = r1;
        }
        __syncthreads();

        k0 += 16;
        if (k0 < K) {
            a0v = *(const float4*)(Ap + k0);
            a1v = *(const float4*)(Ap2 + k0);
            b0v = *(const float4*)(Bp + (size_t)k0 * N);
            b1v = *(const float4*)(Bp2 + (size_t)k0 * N);
        }

#pragma unroll
        for (int kk = 0; kk < 16; kk += 8) {
            const int kq = kk + q;
            uint32_t af[4][4];
            uint32_t bf[4][2];
#pragma unroll
            for (int mt = 0; mt < 4; mt++) {
                const int mr = wm + mt * 16 + g;
                af[mt][0] = __float_as_uint(As[kq][mr]);
                af[mt][1] = __float_as_uint(As[kq][mr + 8]);
                af[mt][2] = __float_as_uint(As[kq + 4][mr]);
                af[mt][3] = __float_as_uint(As[kq + 4][mr + 8]);
            }
#pragma unroll
            for (int nt = 0; nt < 4; nt++) {
                const int nc = wn + nt * 8 + g;
                bf[nt][0] = __float_as_uint(Bs[kq][nc]);
                bf[nt][1] = __float_as_uint(Bs[kq + 4][nc]);
            }
#pragma unroll
            for (int mt = 0; mt < 4; mt++)
#pragma unroll
                for (int nt = 0; nt < 4; nt++)
                    mma_tf32(acc[mt][nt], af[mt], bf[nt]);
        }
        if (k0 >= K) break;
        __syncthreads();
    }

    // epilogue
#pragma unroll
    for (int mt = 0; mt < 4; mt++) {
        const int r0 = bm + wm + mt * 16 + g;
#pragma unroll
        for (int half = 0; half < 2; half++) {
            const int m = r0 + half * 8;
            const size_t rowOff = (size_t)m * N;
            const size_t erow = extra ? (size_t)(m / extraDiv) * N : 0;
            const size_t e2row = extra2 ? (size_t)(m / extra2Div) * N : 0;
#pragma unroll
            for (int nt = 0; nt < 4; nt++) {
                const int n = bn + wn + nt * 8 + q * 2;
                float v0 = acc[mt][nt][half * 2 + 0];
                float v1 = acc[mt][nt][half * 2 + 1];
                if (bias) { v0 += bias[n]; v1 += bias[n + 1]; }
                if (extra) { v0 += extra[erow + n]; v1 += extra[erow + n + 1]; }
                if (extra2) { v0 += extra2[e2row + n]; v1 += extra2[e2row + n + 1]; }
                if (act == 1) { v0 = tanhf(v0); v1 = tanhf(v1); }
                else if (act == 2) { v0 = fmaxf(v0, 0.f); v1 = fmaxf(v1, 0.f); }
                float2 o; o.x = v0; o.y = v1;
                *(float2*)&C[rowOff + n] = o;
            }
        }
    }
}

// ---------------- pointwise kernels ----------------

__global__ void init_kernel(const float* __restrict__ w, const float* __restrict__ mask,
                            float* __restrict__ h, float* __restrict__ c)
{
    int idx = blockIdx.x * blockDim.x + threadIdx.x;
    int row = idx / HQ;
    float sm = 1.f - mask[row];
    float v = w[idx] * sm;
    h[idx] = v;
    c[idx] = v;
}

__global__ void lens_kernel(const float* __restrict__ mask, float* __restrict__ lens)
{
    int b = blockIdx.x, t = threadIdx.x;
    float s = 0.f;
    for (int l = t; l < LQ; l += 256) s += 1.f - mask[b * LQ + l];
    float dummy = 0.f;
    warpRed2(s, dummy);
    __shared__ float ws[8];
    if ((t & 31) == 0) ws[t >> 5] = s;
    __syncthreads();
    if (t == 0) {
        float S = 0.f;
        for (int w = 0; w < 8; w++) S += ws[w];
        lens[b] = S;
    }
}

// out[b,h] = sum_l in[b,l,h] / lens[b]  (o2 optional duplicate)
__global__ void colmean_kernel(const float* __restrict__ in, float* __restrict__ o1,
                               float* __restrict__ o2, const float* __restrict__ lens)
{
    int b = blockIdx.y;
    int hh = blockIdx.x * blockDim.x + threadIdx.x;
    const float* p = in + (size_t)b * LQ * HQ + hh;
    float s = 0.f;
#pragma unroll 8
    for (int l = 0; l < LQ; l++) s += p[(size_t)l * HQ];
    s /= lens[b];
    o1[b * HQ + hh] = s;
    if (o2) o2[b * HQ + hh] = s;
}

// dext[b][n] = bg[n] + sum_i dh[b][i] * Wg[3H+i][n]   (rank-8 d_in contribution, exact fp32)
__global__ void dext_kernel(const float* __restrict__ dh, const float* __restrict__ Wg,
                            const float* __restrict__ bg, float* __restrict__ dext)
{
    int b = blockIdx.y;
    int n = blockIdx.x * 256 + threadIdx.x;    // grid.x = 16 -> 4096 cols
    __shared__ float ds[HQ];
    for (int i = threadIdx.x; i < HQ; i += 256) ds[i] = dh[b * HQ + i];
    __syncthreads();
    const float* W = Wg + (size_t)3 * HQ * (8 * HQ) + n;
    float s = bg[n];
#pragma unroll 8
    for (int i = 0; i < HQ; i++) s += ds[i] * W[(size_t)i * (8 * HQ)];
    dext[(size_t)b * 8 * HQ + n] = s;
}

// Build concat [h, hb, ha] (3H wide) and cb/ca window sums (KERNEL_SIZE=2)
__global__ void build_kernel(const float* __restrict__ h, const float* __restrict__ c,
                             const float* __restrict__ mask,
                             float* __restrict__ A4, float* __restrict__ cb, float* __restrict__ ca)
{
    int row = blockIdx.x;
    int l = row % LQ;
    float sm = 1.f - mask[row];
    size_t base = (size_t)row * HQ;
    size_t arow = (size_t)row * 3 * HQ;
    for (int j = threadIdx.x; j < HQ; j += blockDim.x) {
        float h1 = (l >= 1) ? h[base - (size_t)HQ + j] : 0.f;
        float h2 = (l >= 2) ? h[base - (size_t)2 * HQ + j] : 0.f;
        float h3 = (l + 1 < LQ) ? h[base + (size_t)HQ + j] : 0.f;
        float h4 = (l + 2 < LQ) ? h[base + (size_t)2 * HQ + j] : 0.f;
        float c1 = (l >= 1) ? c[base - (size_t)HQ + j] : 0.f;
        float c2 = (l >= 2) ? c[base - (size_t)2 * HQ + j] : 0.f;
        float c3 = (l + 1 < LQ) ? c[base + (size_t)HQ + j] : 0.f;
        float c4 = (l + 2 < LQ) ? c[base + (size_t)2 * HQ + j] : 0.f;
        A4[arow + j] = h[base + j];
        A4[arow + HQ + j] = (h1 + h2) * sm;
        A4[arow + 2 * HQ + j] = (h3 + h4) * sm;
        cb[base + j] = (c1 + c2) * sm;
        ca[base + j] = (c3 + c4) * sm;
    }
}

// Per-(b,l)-row gate math: 7 LayerNorms over H, sigmoids, 5-way softmax, cell/hidden update.
__global__ void gate_kernel(const float* __restrict__ gates,
                            const float* __restrict__ cb, const float* __restrict__ ca,
                            float* __restrict__ h, float* __restrict__ c,
                            const float* __restrict__ emb, const float* __restrict__ dc,
                            const float* __restrict__ mask,
                            const float* __restrict__ lng, const float* __restrict__ lnb)
{
    int row = blockIdx.x;
    int b = row / LQ;
    int t = threadIdx.x;
    float sm = 1.f - mask[row];
    const float* g = gates + (size_t)row * (8 * HQ);
    float v[8][2];
#pragma unroll
    for (int cc = 0; cc < 8; cc++) {
        v[cc][0] = g[cc * HQ + t];
        v[cc][1] = g[cc * HQ + t + 256];
    }
    __shared__ float ws[7][8], wq[7][8];
    __shared__ float smu[8], srs[8];
    const int cids[7] = {0, 1, 2, 3, 4, 5, 7};
    int lane = t & 31, warp = t >> 5;
#pragma unroll
    for (int ci = 0; ci < 7; ci++) {
        int cc = cids[ci];
        float s = v[cc][0] + v[cc][1];
        float q = v[cc][0] * v[cc][0] + v[cc][1] * v[cc][1];
        warpRed2(s, q);
        if (lane == 0) { ws[ci][warp] = s; wq[ci][warp] = q; }
    }
    __syncthreads();
    if (t < 7) {
        float S = 0.f, Q = 0.f;
#pragma unroll
        for (int w = 0; w < 8; w++) { S += ws[t][w]; Q += wq[t][w]; }
        float mu = S * (1.f / HQ);
        float var = Q * (1.f / HQ) - mu * mu;
        smu[cids[t]] = mu;
        srs[cids[t]] = rsqrtf(var + 1e-5f);
    }
    __syncthreads();
#pragma unroll
    for (int e = 0; e < 2; e++) {
        int j = t + e * 256;
        size_t idx = (size_t)row * HQ + j;
#define LNF(val, cc, li) (lng[(li) * HQ + j] * ((val) - smu[cc]) * srs[cc] + lnb[(li) * HQ + j])
        float gfl = sigmoidf_(LNF(v[0][e], 0, 3));
        float gfr = sigmoidf_(LNF(v[1][e], 1, 4));
        float gfc = sigmoidf_(LNF(v[2][e], 2, 5));
        float gfd = sigmoidf_(LNF(v[3][e], 3, 6));
        float gi  = sigmoidf_(LNF(v[4][e], 4, 0));
        float ge  = sigmoidf_(LNF(v[5][e], 5, 2));
        float go  = sigmoidf_(LNF(v[7][e], 7, 1));
#undef LNF
        float cand = tanhf(v[6][e]);
        float m5 = fmaxf(fmaxf(fmaxf(gfl, gfr), fmaxf(gfc, gfd)), gi);
        float e0 = expf(gfl - m5), e1 = expf(gfr - m5), e2 = expf(gfc - m5);
        float e3 = expf(gfd - m5), e4 = expf(gi - m5);
        float inv = 1.f / (e0 + e1 + e2 + e3 + e4);
        float cold = c[idx];
        float cn = (e0 * cb[idx] + e1 * ca[idx] + e2 * cold + e3 * dc[b * HQ + j] + e4 * cand) * inv;
        float hn = go * tanhf(cn) + ge * emb[idx];
        h[idx] = hn * sm;
        c[idx] = cn * sm;
    }
}

// Tiny decoder matmuls (B=8 rows): g_d, g_do (LN+sigmoid over H), dxf = dh@gWxf
__global__ void small_mm_kernel(const float* __restrict__ dh, const float* __restrict__ avg,
                                const float* __restrict__ Wdg, const float* __restrict__ bdg,
                                const float* __restrict__ Wdf,
                                const float* __restrict__ lng, const float* __restrict__ lnb,
                                float* __restrict__ gd, float* __restrict__ gdo,
                                float* __restrict__ dxf)
{
    int b = blockIdx.x, j = threadIdx.x;   // 512 threads
    __shared__ float ds[HQ], as_[HQ];
    ds[j] = dh[b * HQ + j];
    as_[j] = avg[b * HQ + j];
    __syncthreads();
    float ad = bdg[j], ao = bdg[HQ + j], af = 0.f;
#pragma unroll 4
    for (int i = 0; i < HQ; i++) {
        float d = ds[i], a = as_[i];
        const float* w0 = Wdg + (size_t)i * 2 * HQ;
        const float* w1 = Wdg + (size_t)(HQ + i) * 2 * HQ;
        ad += d * w0[j] + a * w1[j];
        ao += d * w0[HQ + j] + a * w1[HQ + j];
        af += d * Wdf[(size_t)i * HQ + j];
    }
    __shared__ float ws[16], wq[16];
    __shared__ float stat[4];
    int lane = j & 31, warp = j >> 5;
    float s = ad, q = ad * ad;
    warpRed2(s, q);
    if (lane == 0) { ws[warp] = s; wq[warp] = q; }
    __syncthreads();
    if (j == 0) {
        float S = 0.f, Q = 0.f;
        for (int w = 0; w < 16; w++) { S += ws[w]; Q += wq[w]; }
        float mu = S * (1.f / HQ);
        stat[0] = mu;
        stat[1] = rsqrtf(Q * (1.f / HQ) - mu * mu + 1e-5f);
    }
    __syncthreads();
    float gdv = sigmoidf_(lng[7 * HQ + j] * (ad - stat[0]) * stat[1] + lnb[7 * HQ + j]);
    __syncthreads();
    s = ao; q = ao * ao;
    warpRed2(s, q);
    if (lane == 0) { ws[warp] = s; wq[warp] = q; }
    __syncthreads();
    if (j == 0) {
        float S = 0.f, Q = 0.f;
        for (int w = 0; w < 16; w++) { S += ws[w]; Q += wq[w]; }
        float mu = S * (1.f / HQ);
        stat[2] = mu;
        stat[3] = rsqrtf(Q * (1.f / HQ) - mu * mu + 1e-5f);
    }
    __syncthreads();
    float gdov = sigmoidf_(lng[8 * HQ + j] * (ao - stat[2]) * stat[3] + lnb[8 * HQ + j]);
    gd[b * HQ + j] = gdv;
    gdo[b * HQ + j] = gdov;
    dxf[b * HQ + j] = af;
}

// Row LayerNorm over H, optional sigmoid, optional seq_mask multiply.
__global__ void rowln_kernel(const float* __restrict__ in, float* __restrict__ out,
                             const float* __restrict__ lng, const float* __restrict__ lnb,
                             int lnidx, int act, const float* __restrict__ mask)
{
    int row = blockIdx.x, t = threadIdx.x;  // 256 threads
    const float* r = in + (size_t)row * HQ;
    float v0 = r[t], v1 = r[t + 256];
    float s = v0 + v1, q = v0 * v0 + v1 * v1;
    warpRed2(s, q);
    __shared__ float ws[8], wq[8], stat[2];
    int lane = t & 31, warp = t >> 5;
    if (lane == 0) { ws[warp] = s; wq[warp] = q; }
    __syncthreads();
    if (t == 0) {
        float S = 0.f, Q = 0.f;
        for (int w = 0; w < 8; w++) { S += ws[w]; Q += wq[w]; }
        float mu = S * (1.f / HQ);
        stat[0] = mu;
        stat[1] = rsqrtf(Q * (1.f / HQ) - mu * mu + 1e-5f);
    }
    __syncthreads();
    float mu = stat[0], rs = stat[1];
    float msc = mask ? (1.f - mask[row]) : 1.f;
    float y0 = lng[lnidx * HQ + t] * (v0 - mu) * rs + lnb[lnidx * HQ + t];
    float y1 = lng[lnidx * HQ + t + 256] * (v1 - mu) * rs + lnb[lnidx * HQ + t + 256];
    if (act == 1) { y0 = sigmoidf_(y0); y1 = sigmoidf_(y1); }
    out[(size_t)row * HQ + t] = y0 * msc;
    out[(size_t)row * HQ + t + 256] = y1 * msc;
}

// Softmax over the L+1 axis per (b,h) column; update dc and dh.
// All candidate values <= 1 (sigmoid outputs), so use fixed max of 1.0.
__global__ void colsoft_kernel(const float* __restrict__ gf, const float* __restrict__ cbuf,
                               const float* __restrict__ gd, const float* __restrict__ gdo,
                               const float* __restrict__ mask,
                               float* __restrict__ dc, float* __restrict__ dh)
{
    int b = blockIdx.y;
    int hh = blockIdx.x * blockDim.x + threadIdx.x;
    const float* gp = gf + (size_t)b * LQ * HQ + hh;
    const float* cp = cbuf + (size_t)b * LQ * HQ + hh;
    const float* mp = mask + b * LQ;
    float s = 0.f, acc = 0.f;
#pragma unroll 4
    for (int l = 0; l < LQ; l++) {
        float v = gp[(size_t)l * HQ] - mp[l] * 1e25f;
        float e = expf(v - 1.f);
        s += e;
        acc += e * cp[(size_t)l * HQ];
    }
    float dcold = dc[b * HQ + hh];
    float eg = expf(gd[b * HQ + hh] - 1.f);
    s += eg;
    acc += eg * dcold;
    float dcn = acc / s;
    dc[b * HQ + hh] = dcn;
    dh[b * HQ + hh] = gdo[b * HQ + hh] * tanhf(dcn);
}

// ---------------- host side ----------------

static void gemm(const float* A, const float* Bm, float* C, int M, int N, int K,
                 const float* bias, const float* extra, int extraDiv, int act,
                 const float* extra2 = nullptr, int extra2Div = 1)
{
    dim3 grid(N / 128, M / 128);
    gemm_tf32_kernel<<<grid, 256>>>(A, Bm, C, M, N, K, bias, extra, extraDiv, act,
                                    extra2, extra2Div);
}

#define SYM(var, symbol) do { void* _p = nullptr; cudaGetSymbolAddress(&_p, symbol); var = (float*)_p; } while (0)

extern "C" void kernel_launch(void* const* d_in, const int* in_sizes, int n_in,
                              void* d_out, int out_size)
{
    (void)in_sizes; (void)n_in; (void)out_size;
    const float* word = (const float*)d_in[0];
    const float* mask = (const float*)d_in[1];
    // d_in[2] = num_layers (int32, value 3) -> loop count must be host-constant for graph capture
    const float* Wg   = (const float*)d_in[3];
    const float* bg   = (const float*)d_in[4];
    const float* Wemb = (const float*)d_in[5];
    const float* Wdg  = (const float*)d_in[6];
    const float* bdg  = (const float*)d_in[7];
    const float* Wdf  = (const float*)d_in[8];
    const float* bdf  = (const float*)d_in[9];
    const float* Wet  = (const float*)d_in[10];
    const float* bet  = (const float*)d_in[11];
    const float* W1   = (const float*)d_in[12];
    const float* b1   = (const float*)d_in[13];
    const float* W2   = (const float*)d_in[14];
    const float* b2   = (const float*)d_in[15];
    const float* lng  = (const float*)d_in[16];
    const float* lnb  = (const float*)d_in[17];
    float* out = (float*)d_out;

    float *h, *c, *emb, *wecat, *Acat, *gates, *cb, *ca, *gf, *r, *outpre;
    float *dh, *dc, *avg, *gd, *gdo, *dxf, *dext, *lens;
    SYM(h, g_h); SYM(c, g_c); SYM(emb, g_emb); SYM(wecat, g_wecat);
    SYM(Acat, g_Acat); SYM(gates, g_gates); SYM(cb, g_cb); SYM(ca, g_ca);
    SYM(gf, g_gf); SYM(r, g_r); SYM(outpre, g_outpre);
    SYM(dh, g_dh); SYM(dc, g_dc); SYM(avg, g_avg); SYM(gd, g_gd);
    SYM(gdo, g_gdo); SYM(dxf, g_dxf); SYM(dext, g_dext); SYM(lens, g_lens);

    // x = word * seq_mask; h = c = x
    init_kernel<<<(ML * HQ) / 256, 256>>>(word, mask, h, c);
    lens_kernel<<<BQ, 256>>>(mask, lens);
    colmean_kernel<<<dim3(HQ / 256, BQ), 256>>>(h, dh, dc, lens);

    // we_cat = x @ Wemb ;  emb_tr = tanh(x @ Wet + bet)
    gemm(h, Wemb, wecat, ML, 8 * HQ, HQ, nullptr, nullptr, 1, 0);
    gemm(h, Wet, emb, ML, HQ, HQ, bet, nullptr, 1, 1);

    for (int layer = 0; layer < NUM_LAYERS; ++layer) {
        build_kernel<<<ML, 256>>>(h, c, mask, Acat, cb, ca);
        // dext[b] = bg + dh[b] @ Wg[3H:4H]   (rank-8 d_in contribution, fp32)
        dext_kernel<<<dim3(16, BQ), 256>>>(dh, Wg, bg, dext);
        // gates = [h,hb,ha] @ Wg[0:3H] + we_cat + dext[b]
        gemm(Acat, Wg, gates, ML, 8 * HQ, 3 * HQ, nullptr, wecat, 1, 0, dext, LQ);
        gate_kernel<<<ML, 256>>>(gates, cb, ca, h, c, emb, dc, mask, lng, lnb);
        colmean_kernel<<<dim3(HQ / 256, BQ), 256>>>(h, avg, nullptr, lens);
        small_mm_kernel<<<BQ, HQ>>>(dh, avg, Wdg, bdg, Wdf, lng, lnb, gd, gdo, dxf);
        // pre_f = h @ gWhf + bdf + dxf[b]  (gWhf = Wdf rows H..2H)
        gemm(h, Wdf + (size_t)HQ * HQ, gf, ML, HQ, HQ, bdf, dxf, LQ, 0);
        rowln_kernel<<<ML, 256>>>(gf, gf, lng, lnb, 9, 1, nullptr);   // g_f = sigmoid(LN(.))
        colsoft_kernel<<<dim3(HQ / 256, BQ), 256>>>(gf, c, gd, gdo, mask, dc, dh);
    }

    // FFN + residual + final LN * seq_mask
    gemm(h, W1, r, ML, 2 * HQ, HQ, b1, nullptr, 1, 2);           // relu(h@W1+b1)
    gemm(r, W2, outpre, ML, HQ, 2 * HQ, b2, h, 1, 0);            // h + r@W2 + b2
    rowln_kernel<<<ML, 256>>>(outpre, out, lng, lnb, 10, 0, mask);
}

// round 17
// speedup vs baseline: 1.3987x; 1.2142x over previous
#include <cuda_runtime.h>
#include <math.h>
#include <stdint.h>

#define BQ 8
#define LQ 1024
#define HQ 512
#define ML (BQ * LQ)   // 8192 rows
#define NCH 16         // L-reduction chunks
#define LCH (LQ / NCH) // 64 rows per chunk

static const int NUM_LAYERS = 3;

// ---------------- static scratch (no allocations allowed) ----------------
__device__ float g_h[ML * HQ];
__device__ float g_c[ML * HQ];
__device__ float g_emb[ML * HQ];
__device__ float g_wecat[ML * 8 * HQ];   // 134 MB
__device__ float g_Acat[ML * 3 * HQ];    // 50 MB  (d_in folded out)
__device__ float g_gates[ML * 8 * HQ];   // 134 MB
__device__ float g_cb[ML * HQ];
__device__ float g_ca[ML * HQ];
__device__ float g_gf[ML * HQ];
__device__ float g_r[ML * 2 * HQ];
__device__ float g_outpre[ML * HQ];
__device__ float g_dh[BQ * HQ];
__device__ float g_dc[BQ * HQ];
__device__ float g_avg[BQ * HQ];
__device__ float g_gd[BQ * HQ];
__device__ float g_gdo[BQ * HQ];
__device__ float g_dxf[BQ * HQ];
__device__ float g_dext[BQ * 8 * HQ];    // per-batch d_in@Wg3 + bg
__device__ float g_lens[BQ];
__device__ float g_pS[BQ * NCH * HQ];    // partial sums (reduction scratch)
__device__ float g_pA[BQ * NCH * HQ];

__device__ __forceinline__ float sigmoidf_(float x) { return 1.f / (1.f + __expf(-x)); }

__device__ __forceinline__ void warpRed2(float& s, float& q) {
#pragma unroll
    for (int o = 16; o > 0; o >>= 1) {
        s += __shfl_down_sync(0xffffffffu, s, o);
        q += __shfl_down_sync(0xffffffffu, q, o);
    }
}

__device__ __forceinline__ uint32_t f2tf(float f) {
    uint32_t u;
    asm("cvt.rna.tf32.f32 %0, %1;" : "=r"(u) : "f"(f));
    return u;
}

__device__ __forceinline__ void mma_tf32(float* c, const uint32_t* a, const uint32_t* b) {
    asm volatile(
        "mma.sync.aligned.m16n8k8.row.col.f32.tf32.tf32.f32 "
        "{%0,%1,%2,%3}, {%4,%5,%6,%7}, {%8,%9}, {%0,%1,%2,%3};\n"
        : "+f"(c[0]), "+f"(c[1]), "+f"(c[2]), "+f"(c[3])
        : "r"(a[0]), "r"(a[1]), "r"(a[2]), "r"(a[3]), "r"(b[0]), "r"(b[1]));
}

// ---------------- TF32 tensor-core GEMM (FROZEN R14 CONFIG — do not touch) ----
// 128x128 block tile, 256 threads (8 warps, 2x4), 64x32 per warp (4x4 m16n8k8),
// BK=16, single smem buffer + register prefetch, pad-132 k-major smem.
// epilogue: + bias[n] + extra[(m/extraDiv)*N+n] + extra2[(m/extra2Div)*N+n] (opt),
// act: 0 none, 1 tanh, 2 relu
__global__ void __launch_bounds__(256)
gemm_tf32_kernel(const float* __restrict__ A, const float* __restrict__ Bm,
                 float* __restrict__ C, int M, int N, int K,
                 const float* __restrict__ bias, const float* __restrict__ extra,
                 int extraDiv, int act,
                 const float* __restrict__ extra2, int extra2Div)
{
    __shared__ float As[16][132];   // [k][m], padded
    __shared__ float Bs[16][132];   // [k][n], padded

    const int tid = threadIdx.x;
    const int bm = blockIdx.y * 128;
    const int bn = blockIdx.x * 128;
    const int lane = tid & 31;
    const int warp = tid >> 5;
    const int wm = (warp & 1) * 64;
    const int wn = (warp >> 1) * 32;
    const int g = lane >> 2;          // groupID (0..7)
    const int q = lane & 3;           // threadID_in_group (0..3)

    // global load mapping
    const int arow = tid >> 2;        // 0..63
    const int acol = (tid & 3) * 4;   // 0,4,8,12
    const int bkrow = tid >> 5;       // 0..7
    const int bcol = (tid & 31) * 4;

    const float* Ap  = A + (size_t)(bm + arow) * K + acol;
    const float* Ap2 = Ap + (size_t)64 * K;
    const float* Bp  = Bm + (size_t)bkrow * N + bn + bcol;
    const float* Bp2 = Bp + (size_t)8 * N;

    float4 a0v = *(const float4*)Ap;
    float4 a1v = *(const float4*)Ap2;
    float4 b0v = *(const float4*)Bp;
    float4 b1v = *(const float4*)Bp2;

    float acc[4][4][4];
#pragma unroll
    for (int i = 0; i < 4; i++)
#pragma unroll
        for (int j = 0; j < 4; j++)
#pragma unroll
            for (int k = 0; k < 4; k++) acc[i][j][k] = 0.f;

    int k0 = 0;
    for (;;) {
        As[acol + 0][arow] = a0v.x;
        As[acol + 1][arow] = a0v.y;
        As[acol + 2][arow] = a0v.z;
        As[acol + 3][arow] = a0v.w;
        As[acol + 0][arow + 64] = a1v.x;
        As[acol + 1][arow + 64] = a1v.y;
        As[acol + 2][arow + 64] = a1v.z;
        As[acol + 3][arow + 64] = a1v.w;
        *(float4*)&Bs[bkrow][bcol] = b0v;
        *(float4*)&Bs[bkrow + 8][bcol] = b1v;
        __syncthreads();

        k0 += 16;
        if (k0 < K) {
            a0v = *(const float4*)(Ap + k0);
            a1v = *(const float4*)(Ap2 + k0);
            b0v = *(const float4*)(Bp + (size_t)k0 * N);
            b1v = *(const float4*)(Bp2 + (size_t)k0 * N);
        }

#pragma unroll
        for (int kk = 0; kk < 16; kk += 8) {
            const int kq = kk + q;
            uint32_t af[4][4];
            uint32_t bf[4][2];
#pragma unroll
            for (int mt = 0; mt < 4; mt++) {
                const int mr = wm + mt * 16 + g;
                af[mt][0] = f2tf(As[kq][mr]);
                af[mt][1] = f2tf(As[kq][mr + 8]);
                af[mt][2] = f2tf(As[kq + 4][mr]);
                af[mt][3] = f2tf(As[kq + 4][mr + 8]);
            }
#pragma unroll
            for (int nt = 0; nt < 4; nt++) {
                const int nc = wn + nt * 8 + g;
                bf[nt][0] = f2tf(Bs[kq][nc]);
                bf[nt][1] = f2tf(Bs[kq + 4][nc]);
            }
#pragma unroll
            for (int mt = 0; mt < 4; mt++)
#pragma unroll
                for (int nt = 0; nt < 4; nt++)
                    mma_tf32(acc[mt][nt], af[mt], bf[nt]);
        }
        if (k0 >= K) break;
        __syncthreads();
    }

    // epilogue
#pragma unroll
    for (int mt = 0; mt < 4; mt++) {
        const int r0 = bm + wm + mt * 16 + g;
#pragma unroll
        for (int half = 0; half < 2; half++) {
            const int m = r0 + half * 8;
            const size_t rowOff = (size_t)m * N;
            const size_t erow = extra ? (size_t)(m / extraDiv) * N : 0;
            const size_t e2row = extra2 ? (size_t)(m / extra2Div) * N : 0;
#pragma unroll
            for (int nt = 0; nt < 4; nt++) {
                const int n = bn + wn + nt * 8 + q * 2;
                float v0 = acc[mt][nt][half * 2 + 0];
                float v1 = acc[mt][nt][half * 2 + 1];
                if (bias) { v0 += bias[n]; v1 += bias[n + 1]; }
                if (extra) { v0 += extra[erow + n]; v1 += extra[erow + n + 1]; }
                if (extra2) { v0 += extra2[e2row + n]; v1 += extra2[e2row + n + 1]; }
                if (act == 1) { v0 = tanhf(v0); v1 = tanhf(v1); }
                else if (act == 2) { v0 = fmaxf(v0, 0.f); v1 = fmaxf(v1, 0.f); }
                float2 o; o.x = v0; o.y = v1;
                *(float2*)&C[rowOff + n] = o;
            }
        }
    }
}

// ---------------- pointwise kernels ----------------

__global__ void init_kernel(const float* __restrict__ w, const float* __restrict__ mask,
                            float* __restrict__ h, float* __restrict__ c)
{
    int idx = blockIdx.x * blockDim.x + threadIdx.x;
    int row = idx / HQ;
    float sm = 1.f - mask[row];
    float v = w[idx] * sm;
    h[idx] = v;
    c[idx] = v;
}

__global__ void lens_kernel(const float* __restrict__ mask, float* __restrict__ lens)
{
    int b = blockIdx.x, t = threadIdx.x;
    float s = 0.f;
    for (int l = t; l < LQ; l += 256) s += 1.f - mask[b * LQ + l];
    float dummy = 0.f;
    warpRed2(s, dummy);
    __shared__ float ws[8];
    if ((t & 31) == 0) ws[t >> 5] = s;
    __syncthreads();
    if (t == 0) {
        float S = 0.f;
        for (int w = 0; w < 8; w++) S += ws[w];
        lens[b] = S;
    }
}

// -------- two-phase column mean over L (parallelized across NCH chunks) --------
// phase A: partial sums per chunk -> pS
__global__ void colmean_part_kernel(const float* __restrict__ in, float* __restrict__ pS)
{
    int b = blockIdx.y, ch = blockIdx.z;
    int hh = blockIdx.x * 128 + threadIdx.x;
    const float* p = in + (size_t)b * LQ * HQ + (size_t)ch * LCH * HQ + hh;
    float s = 0.f;
#pragma unroll 8
    for (int l = 0; l < LCH; l++) s += p[(size_t)l * HQ];
    pS[((size_t)b * NCH + ch) * HQ + hh] = s;
}
// phase B: combine chunks (fixed order), divide by lens
__global__ void colmean_fin_kernel(const float* __restrict__ pS, float* __restrict__ o1,
                                   float* __restrict__ o2, const float* __restrict__ lens)
{
    int b = blockIdx.y;
    int hh = blockIdx.x * 256 + threadIdx.x;
    const float* p = pS + (size_t)b * NCH * HQ + hh;
    float s = 0.f;
#pragma unroll
    for (int ch = 0; ch < NCH; ch++) s += p[(size_t)ch * HQ];
    s /= lens[b];
    o1[b * HQ + hh] = s;
    if (o2) o2[b * HQ + hh] = s;
}

// dext[b][n] = bg[n] + sum_i dh[b][i] * Wg[3H+i][n]   (rank-8 d_in contribution, exact fp32)
__global__ void dext_kernel(const float* __restrict__ dh, const float* __restrict__ Wg,
                            const float* __restrict__ bg, float* __restrict__ dext)
{
    int b = blockIdx.y;
    int n = blockIdx.x * 256 + threadIdx.x;    // grid.x = 16 -> 4096 cols
    __shared__ float ds[HQ];
    for (int i = threadIdx.x; i < HQ; i += 256) ds[i] = dh[b * HQ + i];
    __syncthreads();
    const float* W = Wg + (size_t)3 * HQ * (8 * HQ) + n;
    float s = bg[n];
#pragma unroll 8
    for (int i = 0; i < HQ; i++) s += ds[i] * W[(size_t)i * (8 * HQ)];
    dext[(size_t)b * 8 * HQ + n] = s;
}

// Build concat [h, hb, ha] (3H wide) and cb/ca window sums (KERNEL_SIZE=2)
__global__ void build_kernel(const float* __restrict__ h, const float* __restrict__ c,
                             const float* __restrict__ mask,
                             float* __restrict__ A4, float* __restrict__ cb, float* __restrict__ ca)
{
    int row = blockIdx.x;
    int l = row % LQ;
    float sm = 1.f - mask[row];
    size_t base = (size_t)row * HQ;
    size_t arow = (size_t)row * 3 * HQ;
    for (int j = threadIdx.x; j < HQ; j += blockDim.x) {
        float h1 = (l >= 1) ? h[base - (size_t)HQ + j] : 0.f;
        float h2 = (l >= 2) ? h[base - (size_t)2 * HQ + j] : 0.f;
        float h3 = (l + 1 < LQ) ? h[base + (size_t)HQ + j] : 0.f;
        float h4 = (l + 2 < LQ) ? h[base + (size_t)2 * HQ + j] : 0.f;
        float c1 = (l >= 1) ? c[base - (size_t)HQ + j] : 0.f;
        float c2 = (l >= 2) ? c[base - (size_t)2 * HQ + j] : 0.f;
        float c3 = (l + 1 < LQ) ? c[base + (size_t)HQ + j] : 0.f;
        float c4 = (l + 2 < LQ) ? c[base + (size_t)2 * HQ + j] : 0.f;
        A4[arow + j] = h[base + j];
        A4[arow + HQ + j] = (h1 + h2) * sm;
        A4[arow + 2 * HQ + j] = (h3 + h4) * sm;
        cb[base + j] = (c1 + c2) * sm;
        ca[base + j] = (c3 + c4) * sm;
    }
}

// Per-(b,l)-row gate math: 7 LayerNorms over H, sigmoids, 5-way softmax, cell/hidden update.
__global__ void gate_kernel(const float* __restrict__ gates,
                            const float* __restrict__ cb, const float* __restrict__ ca,
                            float* __restrict__ h, float* __restrict__ c,
                            const float* __restrict__ emb, const float* __restrict__ dc,
                            const float* __restrict__ mask,
                            const float* __restrict__ lng, const float* __restrict__ lnb)
{
    int row = blockIdx.x;
    int b = row / LQ;
    int t = threadIdx.x;
    float sm = 1.f - mask[row];
    const float* g = gates + (size_t)row * (8 * HQ);
    float v[8][2];
#pragma unroll
    for (int cc = 0; cc < 8; cc++) {
        v[cc][0] = g[cc * HQ + t];
        v[cc][1] = g[cc * HQ + t + 256];
    }
    __shared__ float ws[7][8], wq[7][8];
    __shared__ float smu[8], srs[8];
    const int cids[7] = {0, 1, 2, 3, 4, 5, 7};
    int lane = t & 31, warp = t >> 5;
#pragma unroll
    for (int ci = 0; ci < 7; ci++) {
        int cc = cids[ci];
        float s = v[cc][0] + v[cc][1];
        float q = v[cc][0] * v[cc][0] + v[cc][1] * v[cc][1];
        warpRed2(s, q);
        if (lane == 0) { ws[ci][warp] = s; wq[ci][warp] = q; }
    }
    __syncthreads();
    if (t < 7) {
        float S = 0.f, Q = 0.f;
#pragma unroll
        for (int w = 0; w < 8; w++) { S += ws[t][w]; Q += wq[t][w]; }
        float mu = S * (1.f / HQ);
        float var = Q * (1.f / HQ) - mu * mu;
        smu[cids[t]] = mu;
        srs[cids[t]] = rsqrtf(var + 1e-5f);
    }
    __syncthreads();
#pragma unroll
    for (int e = 0; e < 2; e++) {
        int j = t + e * 256;
        size_t idx = (size_t)row * HQ + j;
#define LNF(val, cc, li) (lng[(li) * HQ + j] * ((val) - smu[cc]) * srs[cc] + lnb[(li) * HQ + j])
        float gfl = sigmoidf_(LNF(v[0][e], 0, 3));
        float gfr = sigmoidf_(LNF(v[1][e], 1, 4));
        float gfc = sigmoidf_(LNF(v[2][e], 2, 5));
        float gfd = sigmoidf_(LNF(v[3][e], 3, 6));
        float gi  = sigmoidf_(LNF(v[4][e], 4, 0));
        float ge  = sigmoidf_(LNF(v[5][e], 5, 2));
        float go  = sigmoidf_(LNF(v[7][e], 7, 1));
#undef LNF
        float cand = tanhf(v[6][e]);
        float m5 = fmaxf(fmaxf(fmaxf(gfl, gfr), fmaxf(gfc, gfd)), gi);
        float e0 = __expf(gfl - m5), e1 = __expf(gfr - m5), e2 = __expf(gfc - m5);
        float e3 = __expf(gfd - m5), e4 = __expf(gi - m5);
        float inv = 1.f / (e0 + e1 + e2 + e3 + e4);
        float cold = c[idx];
        float cn = (e0 * cb[idx] + e1 * ca[idx] + e2 * cold + e3 * dc[b * HQ + j] + e4 * cand) * inv;
        float hn = go * tanhf(cn) + ge * emb[idx];
        h[idx] = hn * sm;
        c[idx] = cn * sm;
    }
}

// Tiny decoder matmuls (B=8 rows): g_d, g_do (LN+sigmoid over H), dxf = dh@gWxf
__global__ void small_mm_kernel(const float* __restrict__ dh, const float* __restrict__ avg,
                                const float* __restrict__ Wdg, const float* __restrict__ bdg,
                                const float* __restrict__ Wdf,
                                const float* __restrict__ lng, const float* __restrict__ lnb,
                                float* __restrict__ gd, float* __restrict__ gdo,
                                float* __restrict__ dxf)
{
    int b = blockIdx.x, j = threadIdx.x;   // 512 threads
    __shared__ float ds[HQ], as_[HQ];
    ds[j] = dh[b * HQ + j];
    as_[j] = avg[b * HQ + j];
    __syncthreads();
    float ad = bdg[j], ao = bdg[HQ + j], af = 0.f;
#pragma unroll 4
    for (int i = 0; i < HQ; i++) {
        float d = ds[i], a = as_[i];
        const float* w0 = Wdg + (size_t)i * 2 * HQ;
        const float* w1 = Wdg + (size_t)(HQ + i) * 2 * HQ;
        ad += d * w0[j] + a * w1[j];
        ao += d * w0[HQ + j] + a * w1[HQ + j];
        af += d * Wdf[(size_t)i * HQ + j];
    }
    __shared__ float ws[16], wq[16];
    __shared__ float stat[4];
    int lane = j & 31, warp = j >> 5;
    float s = ad, q = ad * ad;
    warpRed2(s, q);
    if (lane == 0) { ws[warp] = s; wq[warp] = q; }
    __syncthreads();
    if (j == 0) {
        float S = 0.f, Q = 0.f;
        for (int w = 0; w < 16; w++) { S += ws[w]; Q += wq[w]; }
        float mu = S * (1.f / HQ);
        stat[0] = mu;
        stat[1] = rsqrtf(Q * (1.f / HQ) - mu * mu + 1e-5f);
    }
    __syncthreads();
    float gdv = sigmoidf_(lng[7 * HQ + j] * (ad - stat[0]) * stat[1] + lnb[7 * HQ + j]);
    __syncthreads();
    s = ao; q = ao * ao;
    warpRed2(s, q);
    if (lane == 0) { ws[warp] = s; wq[warp] = q; }
    __syncthreads();
    if (j == 0) {
        float S = 0.f, Q = 0.f;
        for (int w = 0; w < 16; w++) { S += ws[w]; Q += wq[w]; }
        float mu = S * (1.f / HQ);
        stat[2] = mu;
        stat[3] = rsqrtf(Q * (1.f / HQ) - mu * mu + 1e-5f);
    }
    __syncthreads();
    float gdov = sigmoidf_(lng[8 * HQ + j] * (ao - stat[2]) * stat[3] + lnb[8 * HQ + j]);
    gd[b * HQ + j] = gdv;
    gdo[b * HQ + j] = gdov;
    dxf[b * HQ + j] = af;
}

// Row LayerNorm over H, optional sigmoid, optional seq_mask multiply.
__global__ void rowln_kernel(const float* __restrict__ in, float* __restrict__ out,
                             const float* __restrict__ lng, const float* __restrict__ lnb,
                             int lnidx, int act, const float* __restrict__ mask)
{
    int row = blockIdx.x, t = threadIdx.x;  // 256 threads
    const float* r = in + (size_t)row * HQ;
    float v0 = r[t], v1 = r[t + 256];
    float s = v0 + v1, q = v0 * v0 + v1 * v1;
    warpRed2(s, q);
    __shared__ float ws[8], wq[8], stat[2];
    int lane = t & 31, warp = t >> 5;
    if (lane == 0) { ws[warp] = s; wq[warp] = q; }
    __syncthreads();
    if (t == 0) {
        float S = 0.f, Q = 0.f;
        for (int w = 0; w < 8; w++) { S += ws[w]; Q += wq[w]; }
        float mu = S * (1.f / HQ);
        stat[0] = mu;
        stat[1] = rsqrtf(Q * (1.f / HQ) - mu * mu + 1e-5f);
    }
    __syncthreads();
    float mu = stat[0], rs = stat[1];
    float msc = mask ? (1.f - mask[row]) : 1.f;
    float y0 = lng[lnidx * HQ + t] * (v0 - mu) * rs + lnb[lnidx * HQ + t];
    float y1 = lng[lnidx * HQ + t + 256] * (v1 - mu) * rs + lnb[lnidx * HQ + t + 256];
    if (act == 1) { y0 = sigmoidf_(y0); y1 = sigmoidf_(y1); }
    out[(size_t)row * HQ + t] = y0 * msc;
    out[(size_t)row * HQ + t + 256] = y1 * msc;
}

// -------- two-phase column softmax over L+1 (parallelized across NCH chunks) ----
// phase A: per-chunk partial exp-sum and weighted c-sum
__global__ void colsoft_part_kernel(const float* __restrict__ gf, const float* __restrict__ cbuf,
                                    const float* __restrict__ mask,
                                    float* __restrict__ pS, float* __restrict__ pA)
{
    int b = blockIdx.y, ch = blockIdx.z;
    int hh = blockIdx.x * 128 + threadIdx.x;
    size_t off = (size_t)b * LQ * HQ + (size_t)ch * LCH * HQ + hh;
    const float* gp = gf + off;
    const float* cp = cbuf + off;
    const float* mp = mask + b * LQ + ch * LCH;
    float s = 0.f, acc = 0.f;
#pragma unroll 4
    for (int l = 0; l < LCH; l++) {
        float v = gp[(size_t)l * HQ] - mp[l] * 1e25f;
        float e = __expf(v - 1.f);
        s += e;
        acc += e * cp[(size_t)l * HQ];
    }
    size_t sidx = ((size_t)b * NCH + ch) * HQ + hh;
    pS[sidx] = s;
    pA[sidx] = acc;
}
// phase B: combine chunks (fixed order), add dc term, update dc/dh
__global__ void colsoft_fin_kernel(const float* __restrict__ pS, const float* __restrict__ pA,
                                   const float* __restrict__ gd, const float* __restrict__ gdo,
                                   float* __restrict__ dc, float* __restrict__ dh)
{
    int b = blockIdx.y;
    int hh = blockIdx.x * 256 + threadIdx.x;
    const float* ps = pS + (size_t)b * NCH * HQ + hh;
    const float* pa = pA + (size_t)b * NCH * HQ + hh;
    float s = 0.f, acc = 0.f;
#pragma unroll
    for (int ch = 0; ch < NCH; ch++) {
        s += ps[(size_t)ch * HQ];
        acc += pa[(size_t)ch * HQ];
    }
    float dcold = dc[b * HQ + hh];
    float eg = __expf(gd[b * HQ + hh] - 1.f);
    s += eg;
    acc += eg * dcold;
    float dcn = acc / s;
    dc[b * HQ + hh] = dcn;
    dh[b * HQ + hh] = gdo[b * HQ + hh] * tanhf(dcn);
}

// ---------------- host side ----------------

static void gemm(const float* A, const float* Bm, float* C, int M, int N, int K,
                 const float* bias, const float* extra, int extraDiv, int act,
                 const float* extra2 = nullptr, int extra2Div = 1)
{
    dim3 grid(N / 128, M / 128);
    gemm_tf32_kernel<<<grid, 256>>>(A, Bm, C, M, N, K, bias, extra, extraDiv, act,
                                    extra2, extra2Div);
}

#define SYM(var, symbol) do { void* _p = nullptr; cudaGetSymbolAddress(&_p, symbol); var = (float*)_p; } while (0)

extern "C" void kernel_launch(void* const* d_in, const int* in_sizes, int n_in,
                              void* d_out, int out_size)
{
    (void)in_sizes; (void)n_in; (void)out_size;
    const float* word = (const float*)d_in[0];
    const float* mask = (const float*)d_in[1];
    // d_in[2] = num_layers (int32, value 3) -> loop count must be host-constant for graph capture
    const float* Wg   = (const float*)d_in[3];
    const float* bg   = (const float*)d_in[4];
    const float* Wemb = (const float*)d_in[5];
    const float* Wdg  = (const float*)d_in[6];
    const float* bdg  = (const float*)d_in[7];
    const float* Wdf  = (const float*)d_in[8];
    const float* bdf  = (const float*)d_in[9];
    const float* Wet  = (const float*)d_in[10];
    const float* bet  = (const float*)d_in[11];
    const float* W1   = (const float*)d_in[12];
    const float* b1   = (const float*)d_in[13];
    const float* W2   = (const float*)d_in[14];
    const float* b2   = (const float*)d_in[15];
    const float* lng  = (const float*)d_in[16];
    const float* lnb  = (const float*)d_in[17];
    float* out = (float*)d_out;

    float *h, *c, *emb, *wecat, *Acat, *gates, *cb, *ca, *gf, *r, *outpre;
    float *dh, *dc, *avg, *gd, *gdo, *dxf, *dext, *lens, *pS, *pA;
    SYM(h, g_h); SYM(c, g_c); SYM(emb, g_emb); SYM(wecat, g_wecat);
    SYM(Acat, g_Acat); SYM(gates, g_gates); SYM(cb, g_cb); SYM(ca, g_ca);
    SYM(gf, g_gf); SYM(r, g_r); SYM(outpre, g_outpre);
    SYM(dh, g_dh); SYM(dc, g_dc); SYM(avg, g_avg); SYM(gd, g_gd);
    SYM(gdo, g_gdo); SYM(dxf, g_dxf); SYM(dext, g_dext); SYM(lens, g_lens);
    SYM(pS, g_pS); SYM(pA, g_pA);

    const dim3 partGrid(HQ / 128, BQ, NCH);
    const dim3 finGrid(HQ / 256, BQ);

    // x = word * seq_mask; h = c = x
    init_kernel<<<(ML * HQ) / 256, 256>>>(word, mask, h, c);
    lens_kernel<<<BQ, 256>>>(mask, lens);
    colmean_part_kernel<<<partGrid, 128>>>(h, pS);
    colmean_fin_kernel<<<finGrid, 256>>>(pS, dh, dc, lens);

    // we_cat = x @ Wemb ;  emb_tr = tanh(x @ Wet + bet)
    gemm(h, Wemb, wecat, ML, 8 * HQ, HQ, nullptr, nullptr, 1, 0);
    gemm(h, Wet, emb, ML, HQ, HQ, bet, nullptr, 1, 1);

    for (int layer = 0; layer < NUM_LAYERS; ++layer) {
        build_kernel<<<ML, 256>>>(h, c, mask, Acat, cb, ca);
        // dext[b] = bg + dh[b] @ Wg[3H:4H]   (rank-8 d_in contribution, fp32)
        dext_kernel<<<dim3(16, BQ), 256>>>(dh, Wg, bg, dext);
        // gates = [h,hb,ha] @ Wg[0:3H] + we_cat + dext[b]
        gemm(Acat, Wg, gates, ML, 8 * HQ, 3 * HQ, nullptr, wecat, 1, 0, dext, LQ);
        gate_kernel<<<ML, 256>>>(gates, cb, ca, h, c, emb, dc, mask, lng, lnb);
        colmean_part_kernel<<<partGrid, 128>>>(h, pS);
        colmean_fin_kernel<<<finGrid, 256>>>(pS, avg, nullptr, lens);
        small_mm_kernel<<<BQ, HQ>>>(dh, avg, Wdg, bdg, Wdf, lng, lnb, gd, gdo, dxf);
        // pre_f = h @ gWhf + bdf + dxf[b]  (gWhf = Wdf rows H..2H)
        gemm(h, Wdf + (size_t)HQ * HQ, gf, ML, HQ, HQ, bdf, dxf, LQ, 0);
        rowln_kernel<<<ML, 256>>>(gf, gf, lng, lnb, 9, 1, nullptr);   // g_f = sigmoid(LN(.))
        colsoft_part_kernel<<<partGrid, 128>>>(gf, c, mask, pS, pA);
        colsoft_fin_kernel<<<finGrid, 256>>>(pS, pA, gd, gdo, dc, dh);
    }

    // FFN + residual + final LN * seq_mask
    gemm(h, W1, r, ML, 2 * HQ, HQ, b1, nullptr, 1, 2);           // relu(h@W1+b1)
    gemm(r, W2, outpre, ML, HQ, 2 * HQ, b2, h, 1, 0);            // h + r@W2 + b2
    rowln_kernel<<<ML, 256>>>(outpre, out, lng, lnb, 10, 0, mask);
}